// round 14
// baseline (speedup 1.0000x reference)
#include <cuda_runtime.h>
#include <math.h>
#include <stdint.h>

#define FRAMES 12
#define SEQ    576
#define DIM    640
#define HEADS  8
#define HD     80
#define MROWS  (FRAMES * SEQ)   // 6912

// ---------------- scratch (static device globals: allocation-free) ----------
__device__ float g_q[MROWS * DIM];
__device__ float g_k[MROWS * DIM];
__device__ float g_v[MROWS * DIM];
__device__ float g_att[MROWS * DIM];     // tf32-rounded by attention epilogue
__device__ float g_xr[MROWS * DIM];      // tf32-rounded x
__device__ float g_wq_r[DIM * DIM];
__device__ float g_wk_r[DIM * DIM];
__device__ float g_wv_r[DIM * DIM];
__device__ float g_wo_r[DIM * DIM];
__device__ float g_kh[MROWS * DIM];      // K split hi (tf32 in fp32)
__device__ float g_kl[MROWS * DIM];      // K split lo
__device__ float g_vt[DIM * MROWS];      // V transposed [dim][row], tf32-rounded

// ============================ PTX helpers ====================================
__device__ __forceinline__ uint32_t smem_u32(const void* p) {
    uint32_t a;
    asm("{ .reg .u64 t; cvta.to.shared.u64 t, %1; cvt.u32.u64 %0, t; }"
        : "=r"(a) : "l"(p));
    return a;
}

__device__ __forceinline__ uint32_t round_tf32_bits(float v) {
    uint32_t b;
    asm("cvt.rna.tf32.f32 %0, %1;" : "=r"(b) : "f"(v));
    return b;
}

__device__ __forceinline__ void ldmatrix_x4(uint32_t r[4], uint32_t addr) {
    asm volatile("ldmatrix.sync.aligned.m8n8.x4.shared.b16 {%0,%1,%2,%3}, [%4];"
                 : "=r"(r[0]), "=r"(r[1]), "=r"(r[2]), "=r"(r[3])
                 : "r"(addr));
}

__device__ __forceinline__ void mma_tf32(float c[4], const uint32_t a[4],
                                         uint32_t b0, uint32_t b1) {
    asm volatile(
        "mma.sync.aligned.m16n8k8.row.col.f32.tf32.tf32.f32 "
        "{%0,%1,%2,%3}, {%4,%5,%6,%7}, {%8,%9}, {%0,%1,%2,%3};"
        : "+f"(c[0]), "+f"(c[1]), "+f"(c[2]), "+f"(c[3])
        : "r"(a[0]), "r"(a[1]), "r"(a[2]), "r"(a[3]), "r"(b0), "r"(b1));
}

// ============================ preround kernel ================================
__global__ __launch_bounds__(256) void preround(
    const float* __restrict__ x,  const float* __restrict__ wq,
    const float* __restrict__ wk, const float* __restrict__ wv,
    const float* __restrict__ wo)
{
    const float* src; float* dst; int n4;
    switch (blockIdx.y) {
        case 0: src = x;  dst = g_xr;   n4 = MROWS * DIM / 4; break;
        case 1: src = wq; dst = g_wq_r; n4 = DIM * DIM / 4;   break;
        case 2: src = wk; dst = g_wk_r; n4 = DIM * DIM / 4;   break;
        case 3: src = wv; dst = g_wv_r; n4 = DIM * DIM / 4;   break;
        default: src = wo; dst = g_wo_r; n4 = DIM * DIM / 4;  break;
    }
    for (int i = blockIdx.x * blockDim.x + threadIdx.x; i < n4;
         i += gridDim.x * blockDim.x) {
        float4 v = ((const float4*)src)[i];
        float4 o;
        o.x = __uint_as_float(round_tf32_bits(v.x));
        o.y = __uint_as_float(round_tf32_bits(v.y));
        o.z = __uint_as_float(round_tf32_bits(v.z));
        o.w = __uint_as_float(round_tf32_bits(v.w));
        ((float4*)dst)[i] = o;
    }
}

// ===================== mma.sync tf32 GEMM (unchanged, passing) ===============
#define NKC   (DIM / 32)        // 20 k-chunks
#define TILEB 16384             // 128 rows x 128 B (32 tf32)

__device__ __forceinline__ void stage_load(uint32_t sA, uint32_t sB,
                                           const float* __restrict__ Ag,
                                           const float* __restrict__ Bg,
                                           int kc, int tid)
{
    const float* ga = Ag + kc * 32;
    const float* gb = Bg + kc * 32;
#pragma unroll
    for (int i = 0; i < 4; i++) {
        int idx = tid + i * 256;
        int r   = idx >> 3;
        int c   = idx & 7;
        uint32_t off = (uint32_t)(r * 128 + c * 16);
        uint32_t sw  = off ^ ((uint32_t)(r & 7) << 4);
        const float* pa = ga + (size_t)r * DIM + c * 4;
        const float* pb = gb + (size_t)r * DIM + c * 4;
        asm volatile("cp.async.cg.shared.global [%0], [%1], 16;"
                     :: "r"(sA + sw), "l"(pa));
        asm volatile("cp.async.cg.shared.global [%0], [%1], 16;"
                     :: "r"(sB + sw), "l"(pb));
    }
    asm volatile("cp.async.commit_group;" ::: "memory");
}

__device__ __forceinline__ void tc_gemm_body(const float* __restrict__ A,
                                             const float* __restrict__ B,
                                             float* __restrict__ C,
                                             const float* __restrict__ bias)
{
    extern __shared__ char dynsm_raw[];
    const uint32_t sbase = (smem_u32(dynsm_raw) + 1023u) & ~1023u;
    const uint32_t a0s = sbase;
    const uint32_t b0s = sbase + TILEB;
    const uint32_t a1s = sbase + 2 * TILEB;
    const uint32_t b1s = sbase + 3 * TILEB;

    const int tid  = threadIdx.x;
    const int wid  = tid >> 5;
    const int lane = tid & 31;
    const int mw   = wid >> 2;
    const int nw   = wid & 3;
    const int q    = lane >> 3;
    const int rr   = lane & 7;
    const uint32_t xorv = (uint32_t)rr << 4;

    const int rowA  = mw * 64 + (q & 1) * 8 + rr;
    const int cbA   = q >> 1;
    const int rowB  = nw * 32 + (q >> 1) * 8 + rr;
    const int cbB   = q & 1;

    const float* Ag = A + (size_t)blockIdx.y * 128 * DIM;
    const float* Bg = B + (size_t)blockIdx.x * 128 * DIM;

    float acc[4][4][4];
#pragma unroll
    for (int mt = 0; mt < 4; mt++)
#pragma unroll
        for (int nt = 0; nt < 4; nt++)
#pragma unroll
            for (int e = 0; e < 4; e++) acc[mt][nt][e] = 0.f;

    stage_load(a0s, b0s, Ag, Bg, 0, tid);
    stage_load(a1s, b1s, Ag, Bg, 1, tid);

#pragma unroll 1
    for (int t = 0; t < NKC; t++) {
        const int bsel = t & 1;
        const uint32_t sA = bsel ? a1s : a0s;
        const uint32_t sB = bsel ? b1s : b0s;

        if (t + 1 < NKC)
            asm volatile("cp.async.wait_group 1;" ::: "memory");
        else
            asm volatile("cp.async.wait_group 0;" ::: "memory");
        __syncthreads();

#pragma unroll
        for (int kk = 0; kk < 4; kk++) {
            uint32_t afr[4][4];
#pragma unroll
            for (int mt = 0; mt < 4; mt++) {
                uint32_t addr = sA + (uint32_t)((rowA + mt * 16) * 128)
                              + (((uint32_t)(kk * 2 + cbA) * 16) ^ xorv);
                ldmatrix_x4(afr[mt], addr);
            }
            uint32_t bfr[2][4];
#pragma unroll
            for (int jp = 0; jp < 2; jp++) {
                uint32_t addr = sB + (uint32_t)((rowB + jp * 16) * 128)
                              + (((uint32_t)(kk * 2 + cbB) * 16) ^ xorv);
                ldmatrix_x4(bfr[jp], addr);
            }
#pragma unroll
            for (int mt = 0; mt < 4; mt++)
#pragma unroll
                for (int nt = 0; nt < 4; nt++)
                    mma_tf32(acc[mt][nt], afr[mt],
                             bfr[nt >> 1][(nt & 1) * 2],
                             bfr[nt >> 1][(nt & 1) * 2 + 1]);
        }
        __syncthreads();

        if (t + 2 < NKC) stage_load(sA, sB, Ag, Bg, t + 2, tid);
    }

    const int rowBase = blockIdx.y * 128 + mw * 64 + (lane >> 2);
    const int colBase = blockIdx.x * 128 + nw * 32 + (lane & 3) * 2;
#pragma unroll
    for (int nt = 0; nt < 4; nt++) {
        const int col = colBase + nt * 8;
        float bv0 = 0.f, bv1 = 0.f;
        if (bias) { bv0 = bias[col]; bv1 = bias[col + 1]; }
#pragma unroll
        for (int mt = 0; mt < 4; mt++) {
            const int r0 = rowBase + mt * 16;
            float2 v01 = make_float2(acc[mt][nt][0] + bv0, acc[mt][nt][1] + bv1);
            float2 v23 = make_float2(acc[mt][nt][2] + bv0, acc[mt][nt][3] + bv1);
            *(float2*)(C + (size_t)r0 * DIM + col)       = v01;
            *(float2*)(C + (size_t)(r0 + 8) * DIM + col) = v23;
        }
    }
}

__global__ __launch_bounds__(256) void qkv_tc()
{
    const float* B;
    float* C;
    if (blockIdx.z == 0)      { B = g_wq_r; C = g_q; }
    else if (blockIdx.z == 1) { B = g_wk_r; C = g_k; }
    else                      { B = g_wv_r; C = g_v; }
    tc_gemm_body(g_xr, B, C, nullptr);
}

__global__ __launch_bounds__(256) void out_tc(const float* __restrict__ bo,
                                              float* __restrict__ out)
{
    tc_gemm_body(g_att, g_wo_r, out, bo);
}

// ======================= attention prep kernels ==============================
// split K into tf32 hi/lo
__global__ __launch_bounds__(256) void prep_k()
{
    int i = blockIdx.x * blockDim.x + threadIdx.x;   // over MROWS*DIM/4
    float4 v = ((const float4*)g_k)[i];
    float4 h, l;
    h.x = __uint_as_float(round_tf32_bits(v.x)); l.x = __uint_as_float(round_tf32_bits(v.x - h.x));
    h.y = __uint_as_float(round_tf32_bits(v.y)); l.y = __uint_as_float(round_tf32_bits(v.y - h.y));
    h.z = __uint_as_float(round_tf32_bits(v.z)); l.z = __uint_as_float(round_tf32_bits(v.z - h.z));
    h.w = __uint_as_float(round_tf32_bits(v.w)); l.w = __uint_as_float(round_tf32_bits(v.w - h.w));
    ((float4*)g_kh)[i] = h;
    ((float4*)g_kl)[i] = l;
}

// transpose V to [dim][row], tf32-rounded (single rounding of V)
__global__ __launch_bounds__(256) void prep_vt()
{
    __shared__ float t[32][33];
    const int rb = blockIdx.x * 32;
    const int db = blockIdx.y * 32;
    const int tx = threadIdx.x & 31;
    const int ty = threadIdx.x >> 5;
#pragma unroll
    for (int i = 0; i < 4; i++) {
        int r = ty + i * 8;
        t[r][tx] = g_v[(size_t)(rb + r) * DIM + db + tx];
    }
    __syncthreads();
#pragma unroll
    for (int i = 0; i < 4; i++) {
        int d = ty + i * 8;
        float v = t[tx][d];
        g_vt[(size_t)(db + d) * MROWS + rb + tx] =
            __uint_as_float(round_tf32_bits(v));
    }
}

// ==================== tensor-core split-tf32 flash attention =================
// CTA: 128 thr (4 warps over M). Q tile 64x80 (hi/lo), KV blocks of 64.
// QK^T: 3 MMAs (hh,lh,hl). PV: P split in regs (2 MMAs), V single-rounded.
// Strides (floats): Q/K tiles 84 (336B), P/Vt tiles 68 (272B). P aliases Kh.
#define AQ_S  84
#define AP_S  68
#define AT_QH 0
#define AT_QL 5376
#define AT_KH 10752
#define AT_KL 16128
#define AT_VT 21504
#define AT_FLOATS (21504 + 80 * AP_S)      // 26944 floats = 107776 B

__global__ __launch_bounds__(128) void attn_tc()
{
    extern __shared__ float sm[];
    const uint32_t sb  = smem_u32(sm);
    const uint32_t QhB = sb;
    const uint32_t QlB = sb + AT_QL * 4;
    const uint32_t KhB = sb + AT_KH * 4;
    const uint32_t KlB = sb + AT_KL * 4;
    const uint32_t VtB = sb + AT_VT * 4;
    const uint32_t PB  = KhB;                       // P overlays Kh

    const int tid  = threadIdx.x;
    const int w    = tid >> 5;
    const int lane = tid & 31;
    const int q8   = lane >> 3;
    const int rr   = lane & 7;
    const int r4   = lane >> 2;       // row within 8-group
    const int tc   = lane & 3;        // col pair

    const int qb = blockIdx.x;        // 0..8
    const int h  = blockIdx.y;        // 0..7
    const int zf = blockIdx.z;        // heavy frames first
    const int f  = (zf < 8) ? (zf + 4) : (zf - 8);
    const int kvf = (f < 4) ? f : (f & ~3);
    const int nkv = (f < 4) ? SEQ : 4 * SEQ;
    const float scale = rsqrtf((float)HD);

    // ---- stage Q (scaled, split hi/lo) ----
    const float* Qg = g_q + ((size_t)(f * SEQ + qb * 64)) * DIM + h * HD;
#pragma unroll
    for (int it = 0; it < 40; it++) {
        int e = tid + it * 128;           // 0..5119
        int r = e / 80, d = e % 80;
        float qv = Qg[(size_t)r * DIM + d] * scale;
        float hv = __uint_as_float(round_tf32_bits(qv));
        float lv = __uint_as_float(round_tf32_bits(qv - hv));
        sm[AT_QH + r * AQ_S + d] = hv;
        sm[AT_QL + r * AQ_S + d] = lv;
    }

    float m0 = -INFINITY, m1 = -INFINITY, l0 = 0.f, l1 = 0.f;
    float o[10][4];
#pragma unroll
    for (int n = 0; n < 10; n++)
#pragma unroll
        for (int e = 0; e < 4; e++) o[n][e] = 0.f;

    const float* KhG = g_kh + ((size_t)kvf * SEQ) * DIM + h * HD;
    const float* KlG = g_kl + ((size_t)kvf * SEQ) * DIM + h * HD;
    const float* VtG = g_vt + (size_t)h * HD * MROWS + (size_t)kvf * SEQ;

    const uint32_t aoff_base = (uint32_t)((w * 16 + (q8 & 1) * 8 + rr) * 336
                                          + (q8 >> 1) * 16);
    const uint32_t boff_row  = (uint32_t)(((q8 >> 1) * 8 + rr) * 336
                                          + (q8 & 1) * 16);
    const uint32_t poff_base = (uint32_t)((w * 16 + (q8 & 1) * 8 + rr) * 272
                                          + (q8 >> 1) * 16);
    const uint32_t voff_row  = (uint32_t)(((q8 >> 1) * 8 + rr) * 272
                                          + (q8 & 1) * 16);

#pragma unroll 1
    for (int kb = 0; kb < nkv; kb += 64) {
        __syncthreads();                      // prev block done with smem

        // ---- stage K hi/lo + Vt via cp.async ----
#pragma unroll
        for (int i = 0; i < 10; i++) {
            int c = tid + i * 128;            // 0..1279
            int row = c / 20, col = c % 20;
            const float* s1 = KhG + (size_t)(kb + row) * DIM + col * 4;
            const float* s2 = KlG + (size_t)(kb + row) * DIM + col * 4;
            uint32_t d1 = KhB + (uint32_t)(row * 336 + col * 16);
            uint32_t d2 = KlB + (uint32_t)(row * 336 + col * 16);
            asm volatile("cp.async.cg.shared.global [%0], [%1], 16;" :: "r"(d1), "l"(s1));
            asm volatile("cp.async.cg.shared.global [%0], [%1], 16;" :: "r"(d2), "l"(s2));
        }
#pragma unroll
        for (int i = 0; i < 10; i++) {
            int c = tid + i * 128;
            int dim = c / 16, col = c % 16;
            const float* s3 = VtG + (size_t)dim * MROWS + kb + col * 4;
            uint32_t d3 = VtB + (uint32_t)(dim * 272 + col * 16);
            asm volatile("cp.async.cg.shared.global [%0], [%1], 16;" :: "r"(d3), "l"(s3));
        }
        asm volatile("cp.async.commit_group;" ::: "memory");
        asm volatile("cp.async.wait_group 0;" ::: "memory");
        __syncthreads();

        // ---- S = (Q*scale) K^T, split-tf32 (hh + lh + hl) ----
        float s[8][4];
#pragma unroll
        for (int n = 0; n < 8; n++)
#pragma unroll
            for (int e = 0; e < 4; e++) s[n][e] = 0.f;

#pragma unroll
        for (int kc = 0; kc < 10; kc++) {
            uint32_t Ah[4], Al[4];
            uint32_t ao = aoff_base + kc * 32;
            ldmatrix_x4(Ah, QhB + ao);
            ldmatrix_x4(Al, QlB + ao);
#pragma unroll
            for (int jb = 0; jb < 4; jb++) {
                uint32_t Bh[4], Bl[4];
                uint32_t bo_ = (uint32_t)(jb * 16 * 336) + boff_row + kc * 32;
                ldmatrix_x4(Bh, KhB + bo_);
                ldmatrix_x4(Bl, KlB + bo_);
#pragma unroll
                for (int u2 = 0; u2 < 2; u2++) {
                    const int nt = jb * 2 + u2;
                    const int u = u2 * 2;
                    mma_tf32(s[nt], Ah, Bh[u], Bh[u + 1]);
                    mma_tf32(s[nt], Al, Bh[u], Bh[u + 1]);
                    mma_tf32(s[nt], Ah, Bl[u], Bl[u + 1]);
                }
            }
        }
        __syncthreads();                      // all warps done reading Kh/Kl

        // ---- online softmax (rows w*16 + r4, + 8) + write P over Kh ----
#pragma unroll
        for (int i = 0; i < 2; i++) {
            float mcur = i ? m1 : m0;
            float lcur = i ? l1 : l0;
            float mx = -INFINITY;
#pragma unroll
            for (int nt = 0; nt < 8; nt++)
                mx = fmaxf(mx, fmaxf(s[nt][2 * i], s[nt][2 * i + 1]));
            mx = fmaxf(mx, __shfl_xor_sync(0xffffffffu, mx, 1));
            mx = fmaxf(mx, __shfl_xor_sync(0xffffffffu, mx, 2));
            float mn = fmaxf(mcur, mx);
            float corr = __expf(mcur - mn);
            float rs = 0.f;
            float* prow = sm + AT_KH + (w * 16 + r4 + 8 * i) * AP_S + tc * 2;
#pragma unroll
            for (int nt = 0; nt < 8; nt++) {
                float p0 = __expf(s[nt][2 * i] - mn);
                float p1 = __expf(s[nt][2 * i + 1] - mn);
                rs += p0 + p1;
                *(float2*)(prow + nt * 8) = make_float2(p0, p1);
            }
            rs += __shfl_xor_sync(0xffffffffu, rs, 1);
            rs += __shfl_xor_sync(0xffffffffu, rs, 2);
            if (i) { l1 = lcur * corr + rs; m1 = mn; }
            else   { l0 = lcur * corr + rs; m0 = mn; }
#pragma unroll
            for (int n = 0; n < 10; n++) {
                o[n][2 * i]     *= corr;
                o[n][2 * i + 1] *= corr;
            }
        }
        __syncthreads();                      // P visible to all warps

        // ---- O += P V  (P split hi/lo in regs, V single tf32) ----
#pragma unroll
        for (int kc2 = 0; kc2 < 8; kc2++) {
            uint32_t pr[4], ph[4], pl[4];
            ldmatrix_x4(pr, PB + poff_base + kc2 * 32);
#pragma unroll
            for (int e = 0; e < 4; e++) {
                float pf = __uint_as_float(pr[e]);
                ph[e] = round_tf32_bits(pf);
                pl[e] = round_tf32_bits(pf - __uint_as_float(ph[e]));
            }
#pragma unroll
            for (int jv = 0; jv < 5; jv++) {
                uint32_t vf[4];
                uint32_t vo = (uint32_t)(jv * 16 * 272) + voff_row + kc2 * 32;
                ldmatrix_x4(vf, VtB + vo);
#pragma unroll
                for (int u2 = 0; u2 < 2; u2++) {
                    const int nt2 = jv * 2 + u2;
                    const int u = u2 * 2;
                    mma_tf32(o[nt2], ph, vf[u], vf[u + 1]);
                    mma_tf32(o[nt2], pl, vf[u], vf[u + 1]);
                }
            }
        }
    }

    // ---- epilogue: normalize, tf32-round, store ----
    float* Og = g_att + ((size_t)(f * SEQ + qb * 64)) * DIM + h * HD;
    const float inv0 = 1.f / l0;
    const float inv1 = 1.f / l1;
    const int row0 = w * 16 + r4;
#pragma unroll
    for (int n = 0; n < 10; n++) {
        const int col = n * 8 + tc * 2;
        float2 v0, v1;
        v0.x = __uint_as_float(round_tf32_bits(o[n][0] * inv0));
        v0.y = __uint_as_float(round_tf32_bits(o[n][1] * inv0));
        v1.x = __uint_as_float(round_tf32_bits(o[n][2] * inv1));
        v1.y = __uint_as_float(round_tf32_bits(o[n][3] * inv1));
        *(float2*)(Og + (size_t)row0 * DIM + col)       = v0;
        *(float2*)(Og + (size_t)(row0 + 8) * DIM + col) = v1;
    }
}

// ---------------------------------------------------------------------------
extern "C" void kernel_launch(void* const* d_in, const int* in_sizes, int n_in,
                              void* d_out, int out_size)
{
    const float* x  = (const float*)d_in[0];
    const float* Wq = (const float*)d_in[1];
    const float* Wk = (const float*)d_in[2];
    const float* Wv = (const float*)d_in[3];
    const float* Wo = (const float*)d_in[4];
    const float* bo = (const float*)d_in[5];
    float* out = (float*)d_out;

    (void)in_sizes; (void)n_in; (void)out_size;

    const int GEMM_SMEM = 4 * TILEB + 1024;           // 66560 B
    const int ATTN_SMEM = AT_FLOATS * (int)sizeof(float);   // 107776 B
    cudaFuncSetAttribute(qkv_tc, cudaFuncAttributeMaxDynamicSharedMemorySize,
                         GEMM_SMEM);
    cudaFuncSetAttribute(out_tc, cudaFuncAttributeMaxDynamicSharedMemorySize,
                         GEMM_SMEM);
    cudaFuncSetAttribute(attn_tc, cudaFuncAttributeMaxDynamicSharedMemorySize,
                         ATTN_SMEM);

    // 0) tf32-round GEMM inputs (RNA, unbiased)
    preround<<<dim3(512, 5), 256>>>(x, Wq, Wk, Wv, Wo);

    // 1) fused QKV projection, mma.sync tf32
    qkv_tc<<<dim3(DIM / 128, MROWS / 128, 3), 256, GEMM_SMEM>>>();

    // 2a) attention prep: K hi/lo split, V transpose+round
    prep_k<<<MROWS * DIM / 4 / 256, 256>>>();
    prep_vt<<<dim3(MROWS / 32, DIM / 32), 256>>>();

    // 2b) attention, split-tf32 tensor cores (heavy frames first via z-remap)
    attn_tc<<<dim3(SEQ / 64, HEADS, FRAMES), 128, ATTN_SMEM>>>();

    // 3) output projection + bias, mma.sync tf32
    out_tc<<<dim3(DIM / 128, MROWS / 128, 1), 256, GEMM_SMEM>>>(bo, out);
}

// round 15
// speedup vs baseline: 1.0028x; 1.0028x over previous
#include <cuda_runtime.h>
#include <math.h>
#include <stdint.h>

#define FRAMES 12
#define SEQ    576
#define DIM    640
#define HEADS  8
#define HD     80
#define MROWS  (FRAMES * SEQ)   // 6912

// ---------------- scratch (static device globals: allocation-free) ----------
__device__ float g_q[MROWS * DIM];
__device__ float g_k[MROWS * DIM];
__device__ float g_v[MROWS * DIM];
__device__ float g_att[MROWS * DIM];     // tf32-rounded by attention epilogue
__device__ float g_xr[MROWS * DIM];      // tf32-rounded x
__device__ float g_wq_r[DIM * DIM];
__device__ float g_wk_r[DIM * DIM];
__device__ float g_wv_r[DIM * DIM];
__device__ float g_wo_r[DIM * DIM];
__device__ float g_kh[MROWS * DIM];      // K split hi (tf32 in fp32)
__device__ float g_kl[MROWS * DIM];      // K split lo
__device__ float g_vt[DIM * MROWS];      // V transposed [dim][row], tf32-rounded

// ============================ PTX helpers ====================================
__device__ __forceinline__ uint32_t smem_u32(const void* p) {
    uint32_t a;
    asm("{ .reg .u64 t; cvta.to.shared.u64 t, %1; cvt.u32.u64 %0, t; }"
        : "=r"(a) : "l"(p));
    return a;
}

__device__ __forceinline__ uint32_t round_tf32_bits(float v) {
    uint32_t b;
    asm("cvt.rna.tf32.f32 %0, %1;" : "=r"(b) : "f"(v));
    return b;
}

__device__ __forceinline__ void ldmatrix_x4(uint32_t r[4], uint32_t addr) {
    asm volatile("ldmatrix.sync.aligned.m8n8.x4.shared.b16 {%0,%1,%2,%3}, [%4];"
                 : "=r"(r[0]), "=r"(r[1]), "=r"(r[2]), "=r"(r[3])
                 : "r"(addr));
}

__device__ __forceinline__ void mma_tf32(float c[4], const uint32_t a[4],
                                         uint32_t b0, uint32_t b1) {
    asm volatile(
        "mma.sync.aligned.m16n8k8.row.col.f32.tf32.tf32.f32 "
        "{%0,%1,%2,%3}, {%4,%5,%6,%7}, {%8,%9}, {%0,%1,%2,%3};"
        : "+f"(c[0]), "+f"(c[1]), "+f"(c[2]), "+f"(c[3])
        : "r"(a[0]), "r"(a[1]), "r"(a[2]), "r"(a[3]), "r"(b0), "r"(b1));
}

// ============================ preround kernel ================================
__global__ __launch_bounds__(256) void preround(
    const float* __restrict__ x,  const float* __restrict__ wq,
    const float* __restrict__ wk, const float* __restrict__ wv,
    const float* __restrict__ wo)
{
    const float* src; float* dst; int n4;
    switch (blockIdx.y) {
        case 0: src = x;  dst = g_xr;   n4 = MROWS * DIM / 4; break;
        case 1: src = wq; dst = g_wq_r; n4 = DIM * DIM / 4;   break;
        case 2: src = wk; dst = g_wk_r; n4 = DIM * DIM / 4;   break;
        case 3: src = wv; dst = g_wv_r; n4 = DIM * DIM / 4;   break;
        default: src = wo; dst = g_wo_r; n4 = DIM * DIM / 4;  break;
    }
    for (int i = blockIdx.x * blockDim.x + threadIdx.x; i < n4;
         i += gridDim.x * blockDim.x) {
        float4 v = ((const float4*)src)[i];
        float4 o;
        o.x = __uint_as_float(round_tf32_bits(v.x));
        o.y = __uint_as_float(round_tf32_bits(v.y));
        o.z = __uint_as_float(round_tf32_bits(v.z));
        o.w = __uint_as_float(round_tf32_bits(v.w));
        ((float4*)dst)[i] = o;
    }
}

// ===================== mma.sync tf32 GEMM (unchanged, passing) ===============
#define NKC   (DIM / 32)        // 20 k-chunks
#define TILEB 16384             // 128 rows x 128 B (32 tf32)

__device__ __forceinline__ void stage_load(uint32_t sA, uint32_t sB,
                                           const float* __restrict__ Ag,
                                           const float* __restrict__ Bg,
                                           int kc, int tid)
{
    const float* ga = Ag + kc * 32;
    const float* gb = Bg + kc * 32;
#pragma unroll
    for (int i = 0; i < 4; i++) {
        int idx = tid + i * 256;
        int r   = idx >> 3;
        int c   = idx & 7;
        uint32_t off = (uint32_t)(r * 128 + c * 16);
        uint32_t sw  = off ^ ((uint32_t)(r & 7) << 4);
        const float* pa = ga + (size_t)r * DIM + c * 4;
        const float* pb = gb + (size_t)r * DIM + c * 4;
        asm volatile("cp.async.cg.shared.global [%0], [%1], 16;"
                     :: "r"(sA + sw), "l"(pa));
        asm volatile("cp.async.cg.shared.global [%0], [%1], 16;"
                     :: "r"(sB + sw), "l"(pb));
    }
    asm volatile("cp.async.commit_group;" ::: "memory");
}

__device__ __forceinline__ void tc_gemm_body(const float* __restrict__ A,
                                             const float* __restrict__ B,
                                             float* __restrict__ C,
                                             const float* __restrict__ bias)
{
    extern __shared__ char dynsm_raw[];
    const uint32_t sbase = (smem_u32(dynsm_raw) + 1023u) & ~1023u;
    const uint32_t a0s = sbase;
    const uint32_t b0s = sbase + TILEB;
    const uint32_t a1s = sbase + 2 * TILEB;
    const uint32_t b1s = sbase + 3 * TILEB;

    const int tid  = threadIdx.x;
    const int wid  = tid >> 5;
    const int lane = tid & 31;
    const int mw   = wid >> 2;
    const int nw   = wid & 3;
    const int q    = lane >> 3;
    const int rr   = lane & 7;
    const uint32_t xorv = (uint32_t)rr << 4;

    const int rowA  = mw * 64 + (q & 1) * 8 + rr;
    const int cbA   = q >> 1;
    const int rowB  = nw * 32 + (q >> 1) * 8 + rr;
    const int cbB   = q & 1;

    const float* Ag = A + (size_t)blockIdx.y * 128 * DIM;
    const float* Bg = B + (size_t)blockIdx.x * 128 * DIM;

    float acc[4][4][4];
#pragma unroll
    for (int mt = 0; mt < 4; mt++)
#pragma unroll
        for (int nt = 0; nt < 4; nt++)
#pragma unroll
            for (int e = 0; e < 4; e++) acc[mt][nt][e] = 0.f;

    stage_load(a0s, b0s, Ag, Bg, 0, tid);
    stage_load(a1s, b1s, Ag, Bg, 1, tid);

#pragma unroll 1
    for (int t = 0; t < NKC; t++) {
        const int bsel = t & 1;
        const uint32_t sA = bsel ? a1s : a0s;
        const uint32_t sB = bsel ? b1s : b0s;

        if (t + 1 < NKC)
            asm volatile("cp.async.wait_group 1;" ::: "memory");
        else
            asm volatile("cp.async.wait_group 0;" ::: "memory");
        __syncthreads();

#pragma unroll
        for (int kk = 0; kk < 4; kk++) {
            uint32_t afr[4][4];
#pragma unroll
            for (int mt = 0; mt < 4; mt++) {
                uint32_t addr = sA + (uint32_t)((rowA + mt * 16) * 128)
                              + (((uint32_t)(kk * 2 + cbA) * 16) ^ xorv);
                ldmatrix_x4(afr[mt], addr);
            }
            uint32_t bfr[2][4];
#pragma unroll
            for (int jp = 0; jp < 2; jp++) {
                uint32_t addr = sB + (uint32_t)((rowB + jp * 16) * 128)
                              + (((uint32_t)(kk * 2 + cbB) * 16) ^ xorv);
                ldmatrix_x4(bfr[jp], addr);
            }
#pragma unroll
            for (int mt = 0; mt < 4; mt++)
#pragma unroll
                for (int nt = 0; nt < 4; nt++)
                    mma_tf32(acc[mt][nt], afr[mt],
                             bfr[nt >> 1][(nt & 1) * 2],
                             bfr[nt >> 1][(nt & 1) * 2 + 1]);
        }
        __syncthreads();

        if (t + 2 < NKC) stage_load(sA, sB, Ag, Bg, t + 2, tid);
    }

    const int rowBase = blockIdx.y * 128 + mw * 64 + (lane >> 2);
    const int colBase = blockIdx.x * 128 + nw * 32 + (lane & 3) * 2;
#pragma unroll
    for (int nt = 0; nt < 4; nt++) {
        const int col = colBase + nt * 8;
        float bv0 = 0.f, bv1 = 0.f;
        if (bias) { bv0 = bias[col]; bv1 = bias[col + 1]; }
#pragma unroll
        for (int mt = 0; mt < 4; mt++) {
            const int r0 = rowBase + mt * 16;
            float2 v01 = make_float2(acc[mt][nt][0] + bv0, acc[mt][nt][1] + bv1);
            float2 v23 = make_float2(acc[mt][nt][2] + bv0, acc[mt][nt][3] + bv1);
            *(float2*)(C + (size_t)r0 * DIM + col)       = v01;
            *(float2*)(C + (size_t)(r0 + 8) * DIM + col) = v23;
        }
    }
}

__global__ __launch_bounds__(256) void qkv_tc()
{
    const float* B;
    float* C;
    if (blockIdx.z == 0)      { B = g_wq_r; C = g_q; }
    else if (blockIdx.z == 1) { B = g_wk_r; C = g_k; }
    else                      { B = g_wv_r; C = g_v; }
    tc_gemm_body(g_xr, B, C, nullptr);
}

__global__ __launch_bounds__(256) void out_tc(const float* __restrict__ bo,
                                              float* __restrict__ out)
{
    tc_gemm_body(g_att, g_wo_r, out, bo);
}

// ======================= attention prep kernels ==============================
// split K into tf32 hi/lo
__global__ __launch_bounds__(256) void prep_k()
{
    int i = blockIdx.x * blockDim.x + threadIdx.x;   // over MROWS*DIM/4
    float4 v = ((const float4*)g_k)[i];
    float4 h, l;
    h.x = __uint_as_float(round_tf32_bits(v.x)); l.x = __uint_as_float(round_tf32_bits(v.x - h.x));
    h.y = __uint_as_float(round_tf32_bits(v.y)); l.y = __uint_as_float(round_tf32_bits(v.y - h.y));
    h.z = __uint_as_float(round_tf32_bits(v.z)); l.z = __uint_as_float(round_tf32_bits(v.z - h.z));
    h.w = __uint_as_float(round_tf32_bits(v.w)); l.w = __uint_as_float(round_tf32_bits(v.w - h.w));
    ((float4*)g_kh)[i] = h;
    ((float4*)g_kl)[i] = l;
}

// transpose V to [dim][row], tf32-rounded (single rounding of V)
__global__ __launch_bounds__(256) void prep_vt()
{
    __shared__ float t[32][33];
    const int rb = blockIdx.x * 32;
    const int db = blockIdx.y * 32;
    const int tx = threadIdx.x & 31;
    const int ty = threadIdx.x >> 5;
#pragma unroll
    for (int i = 0; i < 4; i++) {
        int r = ty + i * 8;
        t[r][tx] = g_v[(size_t)(rb + r) * DIM + db + tx];
    }
    __syncthreads();
#pragma unroll
    for (int i = 0; i < 4; i++) {
        int d = ty + i * 8;
        float v = t[tx][d];
        g_vt[(size_t)(db + d) * MROWS + rb + tx] =
            __uint_as_float(round_tf32_bits(v));
    }
}

// ==================== tensor-core split-tf32 flash attention =================
// CTA: 128 thr (4 warps over M). Q tile 64x80 (hi/lo), KV blocks of 64.
// QK^T: 3 MMAs (hh,lh,hl). PV: P split in regs (2 MMAs), V single-rounded.
// Strides (floats): Q/K tiles 84 (336B), P/Vt tiles 68 (272B). P aliases Kh.
#define AQ_S  84
#define AP_S  68
#define AT_QH 0
#define AT_QL 5376
#define AT_KH 10752
#define AT_KL 16128
#define AT_VT 21504
#define AT_FLOATS (21504 + 80 * AP_S)      // 26944 floats = 107776 B

__global__ __launch_bounds__(128) void attn_tc()
{
    extern __shared__ float sm[];
    const uint32_t sb  = smem_u32(sm);
    const uint32_t QhB = sb;
    const uint32_t QlB = sb + AT_QL * 4;
    const uint32_t KhB = sb + AT_KH * 4;
    const uint32_t KlB = sb + AT_KL * 4;
    const uint32_t VtB = sb + AT_VT * 4;
    const uint32_t PB  = KhB;                       // P overlays Kh

    const int tid  = threadIdx.x;
    const int w    = tid >> 5;
    const int lane = tid & 31;
    const int q8   = lane >> 3;
    const int rr   = lane & 7;
    const int r4   = lane >> 2;       // row within 8-group
    const int tc   = lane & 3;        // col pair

    const int qb = blockIdx.x;        // 0..8
    const int h  = blockIdx.y;        // 0..7
    const int zf = blockIdx.z;        // heavy frames first
    const int f  = (zf < 8) ? (zf + 4) : (zf - 8);
    const int kvf = (f < 4) ? f : (f & ~3);
    const int nkv = (f < 4) ? SEQ : 4 * SEQ;
    const float scale = rsqrtf((float)HD);

    // ---- stage Q (scaled, split hi/lo) ----
    const float* Qg = g_q + ((size_t)(f * SEQ + qb * 64)) * DIM + h * HD;
#pragma unroll
    for (int it = 0; it < 40; it++) {
        int e = tid + it * 128;           // 0..5119
        int r = e / 80, d = e % 80;
        float qv = Qg[(size_t)r * DIM + d] * scale;
        float hv = __uint_as_float(round_tf32_bits(qv));
        float lv = __uint_as_float(round_tf32_bits(qv - hv));
        sm[AT_QH + r * AQ_S + d] = hv;
        sm[AT_QL + r * AQ_S + d] = lv;
    }

    float m0 = -INFINITY, m1 = -INFINITY, l0 = 0.f, l1 = 0.f;
    float o[10][4];
#pragma unroll
    for (int n = 0; n < 10; n++)
#pragma unroll
        for (int e = 0; e < 4; e++) o[n][e] = 0.f;

    const float* KhG = g_kh + ((size_t)kvf * SEQ) * DIM + h * HD;
    const float* KlG = g_kl + ((size_t)kvf * SEQ) * DIM + h * HD;
    const float* VtG = g_vt + (size_t)h * HD * MROWS + (size_t)kvf * SEQ;

    const uint32_t aoff_base = (uint32_t)((w * 16 + (q8 & 1) * 8 + rr) * 336
                                          + (q8 >> 1) * 16);
    const uint32_t boff_row  = (uint32_t)(((q8 >> 1) * 8 + rr) * 336
                                          + (q8 & 1) * 16);
    const uint32_t poff_base = (uint32_t)((w * 16 + (q8 & 1) * 8 + rr) * 272
                                          + (q8 >> 1) * 16);
    const uint32_t voff_row  = (uint32_t)(((q8 >> 1) * 8 + rr) * 272
                                          + (q8 & 1) * 16);

#pragma unroll 1
    for (int kb = 0; kb < nkv; kb += 64) {
        __syncthreads();                      // prev block done with smem

        // ---- stage K hi/lo + Vt via cp.async ----
#pragma unroll
        for (int i = 0; i < 10; i++) {
            int c = tid + i * 128;            // 0..1279
            int row = c / 20, col = c % 20;
            const float* s1 = KhG + (size_t)(kb + row) * DIM + col * 4;
            const float* s2 = KlG + (size_t)(kb + row) * DIM + col * 4;
            uint32_t d1 = KhB + (uint32_t)(row * 336 + col * 16);
            uint32_t d2 = KlB + (uint32_t)(row * 336 + col * 16);
            asm volatile("cp.async.cg.shared.global [%0], [%1], 16;" :: "r"(d1), "l"(s1));
            asm volatile("cp.async.cg.shared.global [%0], [%1], 16;" :: "r"(d2), "l"(s2));
        }
#pragma unroll
        for (int i = 0; i < 10; i++) {
            int c = tid + i * 128;
            int dim = c / 16, col = c % 16;
            const float* s3 = VtG + (size_t)dim * MROWS + kb + col * 4;
            uint32_t d3 = VtB + (uint32_t)(dim * 272 + col * 16);
            asm volatile("cp.async.cg.shared.global [%0], [%1], 16;" :: "r"(d3), "l"(s3));
        }
        asm volatile("cp.async.commit_group;" ::: "memory");
        asm volatile("cp.async.wait_group 0;" ::: "memory");
        __syncthreads();

        // ---- S = (Q*scale) K^T, split-tf32 (hh + lh + hl) ----
        float s[8][4];
#pragma unroll
        for (int n = 0; n < 8; n++)
#pragma unroll
            for (int e = 0; e < 4; e++) s[n][e] = 0.f;

#pragma unroll
        for (int kc = 0; kc < 10; kc++) {
            uint32_t Ah[4], Al[4];
            uint32_t ao = aoff_base + kc * 32;
            ldmatrix_x4(Ah, QhB + ao);
            ldmatrix_x4(Al, QlB + ao);
#pragma unroll
            for (int jb = 0; jb < 4; jb++) {
                uint32_t Bh[4], Bl[4];
                uint32_t bo_ = (uint32_t)(jb * 16 * 336) + boff_row + kc * 32;
                ldmatrix_x4(Bh, KhB + bo_);
                ldmatrix_x4(Bl, KlB + bo_);
#pragma unroll
                for (int u2 = 0; u2 < 2; u2++) {
                    const int nt = jb * 2 + u2;
                    const int u = u2 * 2;
                    mma_tf32(s[nt], Ah, Bh[u], Bh[u + 1]);
                    mma_tf32(s[nt], Al, Bh[u], Bh[u + 1]);
                    mma_tf32(s[nt], Ah, Bl[u], Bl[u + 1]);
                }
            }
        }
        __syncthreads();                      // all warps done reading Kh/Kl

        // ---- online softmax (rows w*16 + r4, + 8) + write P over Kh ----
#pragma unroll
        for (int i = 0; i < 2; i++) {
            float mcur = i ? m1 : m0;
            float lcur = i ? l1 : l0;
            float mx = -INFINITY;
#pragma unroll
            for (int nt = 0; nt < 8; nt++)
                mx = fmaxf(mx, fmaxf(s[nt][2 * i], s[nt][2 * i + 1]));
            mx = fmaxf(mx, __shfl_xor_sync(0xffffffffu, mx, 1));
            mx = fmaxf(mx, __shfl_xor_sync(0xffffffffu, mx, 2));
            float mn = fmaxf(mcur, mx);
            float corr = __expf(mcur - mn);
            float rs = 0.f;
            float* prow = sm + AT_KH + (w * 16 + r4 + 8 * i) * AP_S + tc * 2;
#pragma unroll
            for (int nt = 0; nt < 8; nt++) {
                float p0 = __expf(s[nt][2 * i] - mn);
                float p1 = __expf(s[nt][2 * i + 1] - mn);
                rs += p0 + p1;
                *(float2*)(prow + nt * 8) = make_float2(p0, p1);
            }
            rs += __shfl_xor_sync(0xffffffffu, rs, 1);
            rs += __shfl_xor_sync(0xffffffffu, rs, 2);
            if (i) { l1 = lcur * corr + rs; m1 = mn; }
            else   { l0 = lcur * corr + rs; m0 = mn; }
#pragma unroll
            for (int n = 0; n < 10; n++) {
                o[n][2 * i]     *= corr;
                o[n][2 * i + 1] *= corr;
            }
        }
        __syncthreads();                      // P visible to all warps

        // ---- O += P V  (P split hi/lo in regs, V single tf32) ----
#pragma unroll
        for (int kc2 = 0; kc2 < 8; kc2++) {
            uint32_t pr[4], ph[4], pl[4];
            ldmatrix_x4(pr, PB + poff_base + kc2 * 32);
#pragma unroll
            for (int e = 0; e < 4; e++) {
                float pf = __uint_as_float(pr[e]);
                ph[e] = round_tf32_bits(pf);
                pl[e] = round_tf32_bits(pf - __uint_as_float(ph[e]));
            }
#pragma unroll
            for (int jv = 0; jv < 5; jv++) {
                uint32_t vf[4];
                uint32_t vo = (uint32_t)(jv * 16 * 272) + voff_row + kc2 * 32;
                ldmatrix_x4(vf, VtB + vo);
#pragma unroll
                for (int u2 = 0; u2 < 2; u2++) {
                    const int nt2 = jv * 2 + u2;
                    const int u = u2 * 2;
                    mma_tf32(o[nt2], ph, vf[u], vf[u + 1]);
                    mma_tf32(o[nt2], pl, vf[u], vf[u + 1]);
                }
            }
        }
    }

    // ---- epilogue: normalize, tf32-round, store ----
    float* Og = g_att + ((size_t)(f * SEQ + qb * 64)) * DIM + h * HD;
    const float inv0 = 1.f / l0;
    const float inv1 = 1.f / l1;
    const int row0 = w * 16 + r4;
#pragma unroll
    for (int n = 0; n < 10; n++) {
        const int col = n * 8 + tc * 2;
        float2 v0, v1;
        v0.x = __uint_as_float(round_tf32_bits(o[n][0] * inv0));
        v0.y = __uint_as_float(round_tf32_bits(o[n][1] * inv0));
        v1.x = __uint_as_float(round_tf32_bits(o[n][2] * inv1));
        v1.y = __uint_as_float(round_tf32_bits(o[n][3] * inv1));
        *(float2*)(Og + (size_t)row0 * DIM + col)       = v0;
        *(float2*)(Og + (size_t)(row0 + 8) * DIM + col) = v1;
    }
}

// ---------------------------------------------------------------------------
extern "C" void kernel_launch(void* const* d_in, const int* in_sizes, int n_in,
                              void* d_out, int out_size)
{
    const float* x  = (const float*)d_in[0];
    const float* Wq = (const float*)d_in[1];
    const float* Wk = (const float*)d_in[2];
    const float* Wv = (const float*)d_in[3];
    const float* Wo = (const float*)d_in[4];
    const float* bo = (const float*)d_in[5];
    float* out = (float*)d_out;

    (void)in_sizes; (void)n_in; (void)out_size;

    const int GEMM_SMEM = 4 * TILEB + 1024;           // 66560 B
    const int ATTN_SMEM = AT_FLOATS * (int)sizeof(float);   // 107776 B
    cudaFuncSetAttribute(qkv_tc, cudaFuncAttributeMaxDynamicSharedMemorySize,
                         GEMM_SMEM);
    cudaFuncSetAttribute(out_tc, cudaFuncAttributeMaxDynamicSharedMemorySize,
                         GEMM_SMEM);
    cudaFuncSetAttribute(attn_tc, cudaFuncAttributeMaxDynamicSharedMemorySize,
                         ATTN_SMEM);

    // 0) tf32-round GEMM inputs (RNA, unbiased)
    preround<<<dim3(512, 5), 256>>>(x, Wq, Wk, Wv, Wo);

    // 1) fused QKV projection, mma.sync tf32
    qkv_tc<<<dim3(DIM / 128, MROWS / 128, 3), 256, GEMM_SMEM>>>();

    // 2a) attention prep: K hi/lo split, V transpose+round
    prep_k<<<MROWS * DIM / 4 / 256, 256>>>();
    prep_vt<<<dim3(MROWS / 32, DIM / 32), 256>>>();

    // 2b) attention, split-tf32 tensor cores (heavy frames first via z-remap)
    attn_tc<<<dim3(SEQ / 64, HEADS, FRAMES), 128, ATTN_SMEM>>>();

    // 3) output projection + bias, mma.sync tf32
    out_tc<<<dim3(DIM / 128, MROWS / 128, 1), 256, GEMM_SMEM>>>(bo, out);
}